// round 17
// baseline (speedup 1.0000x reference)
#include <cuda_runtime.h>
#include <cuda_fp16.h>

// Shapes (fixed by problem)
#define Bb 32
#define Nn 32
#define Ll 512
#define Mm 64
#define Ff 64
#define EPSV 1e-8f

#define CHUNK_L 16
#define NCHUNK  (Ll / CHUNK_L)   // 32
#define PITCH   144              // smem row pitch (128B data + 16B pad)

// Scratch (no cudaMalloc): alpha split hi/lo fp16 [N,L,M] (2 MB each)
__device__ __half g_Ah[Nn * Ll * Mm];
__device__ __half g_Al[Nn * Ll * Mm];
__device__ float g_rdenom[Nn * Mm];

// ---------------------------------------------------------------------------
// PTX helpers
// ---------------------------------------------------------------------------
__device__ __forceinline__ unsigned int cvt2h(float a, float b) {
    // packed mem order: [f16(a), f16(b)]
    unsigned int r;
    asm("cvt.rn.f16x2.f32 %0, %1, %2;" : "=r"(r) : "f"(b), "f"(a));
    return r;
}

#define CP_ASYNC16(dst, src) \
    asm volatile("cp.async.cg.shared.global [%0], [%1], 16;" :: "r"(dst), "l"(src))
#define CP_COMMIT() asm volatile("cp.async.commit_group;")
#define CP_WAIT(N)  asm volatile("cp.async.wait_group %0;" :: "n"(N))

#define STS128(a0, a1, a2, a3, addr) \
    asm volatile("st.shared.v4.b32 [%0], {%1, %2, %3, %4};" \
                 :: "r"(addr), "r"(a0), "r"(a1), "r"(a2), "r"(a3) : "memory")

#define LDSM4T(r0, r1, r2, r3, addr) \
    asm volatile("ldmatrix.sync.aligned.m8n8.x4.trans.shared.b16 {%0,%1,%2,%3}, [%4];" \
                 : "=r"(r0), "=r"(r1), "=r"(r2), "=r"(r3) : "r"(addr))

#define MMA16816(d, a, b0, b1) \
    asm volatile("mma.sync.aligned.m16n8k16.row.col.f32.f16.f16.f32 " \
                 "{%0,%1,%2,%3}, {%4,%5,%6,%7}, {%8,%9}, {%0,%1,%2,%3};" \
                 : "+f"((d)[0]), "+f"((d)[1]), "+f"((d)[2]), "+f"((d)[3]) \
                 : "r"((a)[0]), "r"((a)[1]), "r"((a)[2]), "r"((a)[3]), \
                   "r"(b0), "r"(b1))

// ---------------------------------------------------------------------------
// Kernel 1: alpha + fp16 hi/lo split. grid (8, 32) x 256 threads.
// ---------------------------------------------------------------------------
__global__ void __launch_bounds__(256) alpha_kernel(
    const float* __restrict__ t,       // [L,1]
    const float* __restrict__ t_left,  // [N,M]
    const float* __restrict__ t_right, // [N,M]
    const float* __restrict__ kappa)   // [N,1]
{
    const int n  = blockIdx.y;
    const int l0 = blockIdx.x * 64;
    const int tid = threadIdx.x;
    const int m  = tid & 63;
    const int ls = tid >> 6;   // 0..3

    const float ka = kappa[n];
    const float k  = (ka > 20.0f) ? ka : log1pf(expf(ka));
    const float invk = 1.0f / k;
    const float tlv = t_left [n * Mm + m];
    const float trv = t_right[n * Mm + m];

    __half* __restrict__ ah = g_Ah + (size_t)(n * Ll) * Mm;
    __half* __restrict__ al = g_Al + (size_t)(n * Ll) * Mm;

#pragma unroll
    for (int j = 0; j < 16; j++) {
        const int l = l0 + ls + 4 * j;
        const float tv = t[l];
        const float e1 = __expf((tv - trv) * invk);
        const float e2 = __expf((tlv - tv) * invk);
        const float a  = __fdividef(1.0f, 1.0f + e1) * __fdividef(1.0f, 1.0f + e2);
        const __half hb = __float2half_rn(a);
        const float hf = __half2float(hb);
        ah[(size_t)l * Mm + m] = hb;
        al[(size_t)l * Mm + m] = __float2half_rn(a - hf);
    }
}

// ---------------------------------------------------------------------------
// Kernel 2: rdenom[n,m] = 1/(sum_l (hi+lo) + EPS). grid 32 x 256 threads.
// hi+lo reproduces alpha to ~2^-22 relative — far below the 1e-3 tolerance.
// ---------------------------------------------------------------------------
__global__ void __launch_bounds__(256) denom_kernel()
{
    const int n = blockIdx.x;
    const int tid = threadIdx.x;
    const int m  = tid & 63;
    const int ls = tid >> 6;

    const __half* __restrict__ ah = g_Ah + (size_t)(n * Ll) * Mm;
    const __half* __restrict__ al = g_Al + (size_t)(n * Ll) * Mm;

    float s = 0.0f;
#pragma unroll 8
    for (int l = ls; l < Ll; l += 4)
        s += __half2float(ah[(size_t)l * Mm + m]) +
             __half2float(al[(size_t)l * Mm + m]);

    __shared__ float red[256];
    red[tid] = s;
    __syncthreads();
    if (ls == 0)
        g_rdenom[n * Mm + m] =
            1.0f / (red[m] + red[m + 64] + red[m + 128] + red[m + 192] + EPSV);
}

// ---------------------------------------------------------------------------
// Kernel 3: mma.sync fp16 2-term split GEMM.
// CTA per (b-pair, n): grid (16, 32), 128 threads / 4 warps.
// Warp w = (m-half mh, f-half fh): 32m x 32f x BOTH b, 2 terms.
// Per warp-chunk: 8 LDSM.x4 (4 A + 4 B) + 32 MMA.
// D += Ahi*X + Alo*X, X single fp16, fp32 accum.
// ---------------------------------------------------------------------------
__global__ void __launch_bounds__(128) gemm_kernel(
    const float* __restrict__ x,   // [B,N,L,F]
    float* __restrict__ out)       // [B,N,M,F]
{
    const int bp = blockIdx.x;
    const int n  = blockIdx.y;
    const int tid = threadIdx.x;
    const int lane = tid & 31;
    const int w  = tid >> 5;
    const int mh = w >> 1;         // m-half (0: m 0-31, 1: m 32-63)
    const int fh = w & 1;          // f-half

    __shared__ __align__(16) unsigned char Ah_s[2][CHUNK_L * PITCH];
    __shared__ __align__(16) unsigned char Al_s[2][CHUNK_L * PITCH];
    __shared__ __align__(16) unsigned char X_s[2][2][CHUNK_L * PITCH]; // [st][b]

    const char* __restrict__ xg[2] = {
        (const char*)(x + (size_t)(((2 * bp + 0) * Nn + n) * Ll) * Ff),
        (const char*)(x + (size_t)(((2 * bp + 1) * Nn + n) * Ll) * Ff) };
    const char* __restrict__ agH = (const char*)(g_Ah + (size_t)(n * Ll) * Mm);
    const char* __restrict__ agL = (const char*)(g_Al + (size_t)(n * Ll) * Mm);

    unsigned int sAh[2], sAl[2], sX[2][2];
#pragma unroll
    for (int s = 0; s < 2; s++) {
        sAh[s] = (unsigned int)__cvta_generic_to_shared(&Ah_s[s][0]);
        sAl[s] = (unsigned int)__cvta_generic_to_shared(&Al_s[s][0]);
#pragma unroll
        for (int b = 0; b < 2; b++)
            sX[s][b] = (unsigned int)__cvta_generic_to_shared(&X_s[s][b][0]);
    }

    // cp.async A roles: 128 threads x 16B covers one 16x64 fp16 tile (2 KB)
    const int arow = tid >> 3, aseg = tid & 7;
    // x conversion roles: 64 threads per b, each 16 f32 of one l-row
    const int bh_t = tid >> 6;
    const int jj = tid & 63;
    const int lrow = jj >> 2;
    const int xf0 = (jj & 3) * 16;

    auto prefetchA = [&](int chunk, int st) {
        const size_t off = ((size_t)(chunk * CHUNK_L + arow) * Mm + aseg * 8) * 2;
        const unsigned int d = arow * PITCH + aseg * 16;
        CP_ASYNC16(sAh[st] + d, agH + off);
        CP_ASYNC16(sAl[st] + d, agL + off);
        CP_COMMIT();
    };

    // ldmatrix per-lane byte offsets (geometry validated in R15/R16)
    // A tile [k16][m64]: frag for m-chunk c (16 m) at abase + 32*c
    const unsigned int abase =
        ((lane & 7) + ((lane >> 4) & 1) * 8) * PITCH + ((lane >> 3) & 1) * 16;
    // B tile [k16][f64]: frag group for f-chunk c (16 f) at bbase + 32*c
    const unsigned int bbase =
        ((lane & 7) + ((lane >> 3) & 1) * 8) * PITCH + (lane >> 4) * 16;

    float acc[2][2][4][4];   // [b][m-tile g][n8 idx][frag]
#pragma unroll
    for (int b = 0; b < 2; b++)
#pragma unroll
        for (int g = 0; g < 2; g++)
#pragma unroll
            for (int j = 0; j < 4; j++)
#pragma unroll
                for (int i = 0; i < 4; i++) acc[b][g][j][i] = 0.0f;

    float4 xr[4];
#pragma unroll
    for (int q = 0; q < 4; q++)
        xr[q] = *(const float4*)(xg[bh_t] + ((size_t)lrow * Ff + xf0 + 4 * q) * 4);

    prefetchA(0, 0);

    for (int c = 0; c < NCHUNK; c++) {
        const int s = c & 1;
        if (c + 1 < NCHUNK) {
            prefetchA(c + 1, s ^ 1);
            CP_WAIT(1);
        } else {
            CP_WAIT(0);
        }

        // convert this chunk's x regs -> single fp16 smem tile
        {
            unsigned int hv[8];
#pragma unroll
            for (int q = 0; q < 4; q++) {
                hv[2 * q]     = cvt2h(xr[q].x, xr[q].y);
                hv[2 * q + 1] = cvt2h(xr[q].z, xr[q].w);
            }
            const unsigned int dX = sX[s][bh_t] + lrow * PITCH + xf0 * 2;
            STS128(hv[0], hv[1], hv[2], hv[3], dX);
            STS128(hv[4], hv[5], hv[6], hv[7], dX + 16);
        }
        // prefetch next chunk's x into regs (overlaps MMA)
        if (c + 1 < NCHUNK) {
#pragma unroll
            for (int q = 0; q < 4; q++)
                xr[q] = *(const float4*)(xg[bh_t] +
                    ((size_t)((c + 1) * CHUNK_L + lrow) * Ff + xf0 + 4 * q) * 4);
        }
        __syncthreads();

        // compute on stage s: A frags for this warp's 32 m (hi+lo),
        // B frags for this warp's 32 f, both b.
        unsigned int ah[2][4], al[2][4];
#pragma unroll
        for (int g = 0; g < 2; g++) {
            const unsigned int ao = abase + 32 * (2 * mh + g);
            LDSM4T(ah[g][0], ah[g][1], ah[g][2], ah[g][3], sAh[s] + ao);
            LDSM4T(al[g][0], al[g][1], al[g][2], al[g][3], sAl[s] + ao);
        }
#pragma unroll
        for (int b = 0; b < 2; b++) {
#pragma unroll
            for (int j = 0; j < 2; j++) {      // f-group (16 f each)
                unsigned int bf[4];
                LDSM4T(bf[0], bf[1], bf[2], bf[3],
                       sX[s][b] + bbase + 32 * (2 * fh + j));
#pragma unroll
                for (int g = 0; g < 2; g++) {  // m-tile
                    MMA16816(acc[b][g][2 * j],     ah[g], bf[0], bf[1]);
                    MMA16816(acc[b][g][2 * j],     al[g], bf[0], bf[1]);
                    MMA16816(acc[b][g][2 * j + 1], ah[g], bf[2], bf[3]);
                    MMA16816(acc[b][g][2 * j + 1], al[g], bf[2], bf[3]);
                }
            }
        }
        __syncthreads();
    }

    // Epilogue: D frag (m16n8): d0,d1 -> (row, c0/c0+1); d2,d3 -> (row+8, ...)
    const int row = lane >> 2;
    const int c0  = (lane & 3) * 2;
    float rd0[2], rd1[2];
#pragma unroll
    for (int g = 0; g < 2; g++) {
        rd0[g] = g_rdenom[n * Mm + 32 * mh + 16 * g + row];
        rd1[g] = g_rdenom[n * Mm + 32 * mh + 16 * g + row + 8];
    }
#pragma unroll
    for (int b = 0; b < 2; b++) {
        float* __restrict__ og =
            out + (size_t)(((2 * bp + b) * Nn + n) * Mm) * Ff;
#pragma unroll
        for (int g = 0; g < 2; g++) {
            const int mrow = 32 * mh + 16 * g + row;
#pragma unroll
            for (int j = 0; j < 4; j++) {
                const int f = 32 * fh + 8 * j + c0;
                float2 p0, p1;
                p0.x = acc[b][g][j][0] * rd0[g];
                p0.y = acc[b][g][j][1] * rd0[g];
                p1.x = acc[b][g][j][2] * rd1[g];
                p1.y = acc[b][g][j][3] * rd1[g];
                *(float2*)&og[mrow * Ff + f]       = p0;
                *(float2*)&og[(mrow + 8) * Ff + f] = p1;
            }
        }
    }
}

// ---------------------------------------------------------------------------
// Launch: alpha -> denom -> gemm (sequential, graph-capturable)
// Inputs (metadata order): x_aug, t, t_left, t_right, kappa
// ---------------------------------------------------------------------------
extern "C" void kernel_launch(void* const* d_in, const int* in_sizes, int n_in,
                              void* d_out, int out_size)
{
    (void)in_sizes; (void)n_in; (void)out_size;
    const float* x       = (const float*)d_in[0];
    const float* t       = (const float*)d_in[1];
    const float* t_left  = (const float*)d_in[2];
    const float* t_right = (const float*)d_in[3];
    const float* kappa   = (const float*)d_in[4];
    float* out = (float*)d_out;

    alpha_kernel<<<dim3(8, Nn), 256>>>(t, t_left, t_right, kappa);
    denom_kernel<<<Nn, 256>>>();
    gemm_kernel<<<dim3(Bb / 2, Nn), 128>>>(x, out);
}